// round 15
// baseline (speedup 1.0000x reference)
#include <cuda_runtime.h>
#include <cuda_bf16.h>
#include <math.h>

#define Sc 1024
#define Hc 16
#define SHIFT 20.0f

// Scratch (static device globals — allocation-free rule)
__device__ unsigned g_qf[(size_t)64 * 64 * 4 * 32 * 8];     // Q frag-linear 16MB
__device__ unsigned g_kf[(size_t)64 * 1024 * 64];           // K rows 16MB
__device__ unsigned g_vt[(size_t)64 * 16 * 64 * 64];        // V tf32 16MB
__device__ float    g_o [(size_t)4 * 1024 * 1024];          // concat 16MB
__device__ unsigned g_mb[1024][32];                         // mask bitwords
// pre-split activations (bf16x2 kpairs): [4096][512]
__device__ unsigned g_aqh[(size_t)4096 * 512];
__device__ unsigned g_aql[(size_t)4096 * 512];
__device__ unsigned g_akh[(size_t)4096 * 512];
__device__ unsigned g_akl[(size_t)4096 * 512];
// pre-split weights: [16][512][64]
__device__ unsigned g_wqh[(size_t)16 * 512 * 64];
__device__ unsigned g_wql[(size_t)16 * 512 * 64];
__device__ unsigned g_wkh[(size_t)16 * 512 * 64];
__device__ unsigned g_wkl[(size_t)16 * 512 * 64];

__device__ __forceinline__ unsigned f2tf(float x) {
    unsigned r; asm("cvt.rna.tf32.f32 %0, %1;" : "=r"(r) : "f"(x)); return r;
}
__device__ __forceinline__ unsigned pack_bf(float e, float o) {
    unsigned r; asm("cvt.rn.bf16x2.f32 %0, %1, %2;" : "=r"(r) : "f"(o), "f"(e)); return r;
}
__device__ __forceinline__ void split_pack(float e, float o, unsigned& hp, unsigned& lp) {
    hp = pack_bf(e, o);
    float eh = __uint_as_float(hp << 16);
    float oh = __uint_as_float(hp & 0xffff0000u);
    lp = pack_bf(e - eh, o - oh);
}
__device__ __forceinline__ void mma_tf(float& c0, float& c1, float& c2, float& c3,
                                       unsigned a0, unsigned a1, unsigned a2, unsigned a3,
                                       unsigned b0, unsigned b1) {
    asm volatile("mma.sync.aligned.m16n8k8.row.col.f32.tf32.tf32.f32 "
                 "{%0,%1,%2,%3},{%4,%5,%6,%7},{%8,%9},{%0,%1,%2,%3};"
                 : "+f"(c0), "+f"(c1), "+f"(c2), "+f"(c3)
                 : "r"(a0), "r"(a1), "r"(a2), "r"(a3), "r"(b0), "r"(b1));
}
__device__ __forceinline__ void mma_bf(float& c0, float& c1, float& c2, float& c3,
                                       unsigned a0, unsigned a1, unsigned a2, unsigned a3,
                                       unsigned b0, unsigned b1) {
    asm volatile("mma.sync.aligned.m16n8k16.row.col.f32.bf16.bf16.f32 "
                 "{%0,%1,%2,%3},{%4,%5,%6,%7},{%8,%9},{%0,%1,%2,%3};"
                 : "+f"(c0), "+f"(c1), "+f"(c2), "+f"(c3)
                 : "r"(a0), "r"(a1), "r"(a2), "r"(a3), "r"(b0), "r"(b1));
}
__device__ __forceinline__ void cp16(void* smem_dst, const void* gmem_src) {
    unsigned d = (unsigned)__cvta_generic_to_shared(smem_dst);
    asm volatile("cp.async.cg.shared.global [%0], [%1], 16;"
                 :: "r"(d), "l"(gmem_src) : "memory");
}

// ---------------------------------------------------------------------------
__global__ void maskbits_kernel(const int* __restrict__ mask)
{
    const int r = blockIdx.x;
    const int c = threadIdx.x;
    unsigned b = __ballot_sync(0xffffffffu, mask[(size_t)r * 1024 + c] != 0);
    if ((c & 31) == 0) g_mb[r][c >> 5] = b;
}

// ---------------------------------------------------------------------------
// Pre-split activations: A[4096][1024] f32 -> hi/lo bf16x2 kpairs [4096][512]
// ---------------------------------------------------------------------------
__global__ __launch_bounds__(256) void split_act(
    const float* __restrict__ Aq, const float* __restrict__ Ak)
{
    const float* A = blockIdx.z ? Ak : Aq;
    unsigned* oh = blockIdx.z ? g_akh : g_aqh;
    unsigned* ol = blockIdx.z ? g_akl : g_aql;
    const int row = blockIdx.x, t = threadIdx.x;
    float4 v = *reinterpret_cast<const float4*>(&A[(size_t)row * 1024 + t * 4]);
    unsigned h0, l0, h1, l1;
    split_pack(v.x, v.y, h0, l0);
    split_pack(v.z, v.w, h1, l1);
    *reinterpret_cast<uint2*>(&oh[(size_t)row * 512 + t * 2]) = make_uint2(h0, h1);
    *reinterpret_cast<uint2*>(&ol[(size_t)row * 512 + t * 2]) = make_uint2(l0, l1);
}

// ---------------------------------------------------------------------------
// Pre-split weights: W[16][1024][64] -> hi/lo [16][512][64] (adjacent-d pairs)
// ---------------------------------------------------------------------------
__global__ void split_wgt(const float* __restrict__ Wq, const float* __restrict__ Wk)
{
    const float* W = blockIdx.z ? Wk : Wq;
    unsigned* oh = blockIdx.z ? g_wkh : g_wqh;
    unsigned* ol = blockIdx.z ? g_wkl : g_wql;
    const int kp = blockIdx.x, h = blockIdx.y, n = threadIdx.x;
    float a = W[((size_t)h * 1024 + 2 * kp) * 64 + n];
    float b = W[((size_t)h * 1024 + 2 * kp + 1) * 64 + n];
    unsigned hp, lp;
    split_pack(a, b, hp, lp);
    oh[((size_t)h * 512 + kp) * 64 + n] = hp;
    ol[((size_t)h * 512 + kp) * 64 + n] = lp;
}

// ---------------------------------------------------------------------------
// QKV projections in ONE launch. z=0/1: Q/K — pre-split operands, cp.async
// double-buffered staging (1 barrier/iter). z=2: V — tf32 single (R13 body).
// Dynamic smem: QK 2 x 9344 words = 74752 B; V uses first 9344 words.
// ---------------------------------------------------------------------------
#define QKV_SMEM 74752

__global__ __launch_bounds__(256, 2) void qkv_proj(
    const float* __restrict__ Av,
    const float* __restrict__ Wv,
    const float* __restrict__ bq, const float* __restrict__ bk,
    const float* __restrict__ bv,
    unsigned* __restrict__ outQ, unsigned* __restrict__ outK,
    unsigned* __restrict__ outV)
{
    extern __shared__ unsigned sm[];

    const int tid  = threadIdx.x;
    const int lane = tid & 31, warp = tid >> 5;
    const int g = lane >> 2, tig = lane & 3;
    const int wm = warp >> 1, wn = warp & 1;
    const int cRow = blockIdx.y, cCol = blockIdx.x;
    const int zz = blockIdx.z;

    float acc[2][8][4];
#pragma unroll
    for (int i = 0; i < 2; i++)
#pragma unroll
        for (int j = 0; j < 8; j++)
#pragma unroll
            for (int l = 0; l < 4; l++) acc[i][j][l] = 0.f;

    if (zz == 2) {
        // ================= V path: single TF32, Kt=16 (R13 body) ============
        unsigned (*Ah)[20]  = reinterpret_cast<unsigned(*)[20]>(sm);
        unsigned (*Bh)[136] = reinterpret_cast<unsigned(*)[136]>(sm + 2560);

        const float* A = Av; const float* W = Wv; const float* bias = bv;

        const int aR0 = tid >> 2,         aC0 = (tid & 3) * 4;
        const int aR1 = (tid + 256) >> 2, aC1 = aC0;
        const int bD0 = tid >> 5,         bN0 = (tid & 31) * 4;
        const int bD1 = (tid + 256) >> 5, bN1 = bN0;
        const int n0g = cCol * 128 + bN0, h0 = n0g >> 6, kk0 = n0g & 63;

        float4 aP0 = *reinterpret_cast<const float4*>(&A[(size_t)(cRow * 128 + aR0) * 1024 + aC0]);
        float4 aP1 = *reinterpret_cast<const float4*>(&A[(size_t)(cRow * 128 + aR1) * 1024 + aC1]);
        float4 wP0 = *reinterpret_cast<const float4*>(&W[((size_t)h0 * 1024 + bD0) * 64 + kk0]);
        float4 wP1 = *reinterpret_cast<const float4*>(&W[((size_t)h0 * 1024 + bD1) * 64 + kk0]);

        for (int k0 = 0; k0 < 1024; k0 += 16) {
            *reinterpret_cast<uint4*>(&Ah[aR0][aC0]) =
                make_uint4(f2tf(aP0.x), f2tf(aP0.y), f2tf(aP0.z), f2tf(aP0.w));
            *reinterpret_cast<uint4*>(&Ah[aR1][aC1]) =
                make_uint4(f2tf(aP1.x), f2tf(aP1.y), f2tf(aP1.z), f2tf(aP1.w));
            *reinterpret_cast<uint4*>(&Bh[bD0][bN0]) =
                make_uint4(f2tf(wP0.x), f2tf(wP0.y), f2tf(wP0.z), f2tf(wP0.w));
            *reinterpret_cast<uint4*>(&Bh[bD1][bN1]) =
                make_uint4(f2tf(wP1.x), f2tf(wP1.y), f2tf(wP1.z), f2tf(wP1.w));
            __syncthreads();

            if (k0 + 16 < 1024) {
                const int kn = k0 + 16;
                aP0 = *reinterpret_cast<const float4*>(&A[(size_t)(cRow * 128 + aR0) * 1024 + kn + aC0]);
                aP1 = *reinterpret_cast<const float4*>(&A[(size_t)(cRow * 128 + aR1) * 1024 + kn + aC1]);
                wP0 = *reinterpret_cast<const float4*>(&W[((size_t)h0 * 1024 + kn + bD0) * 64 + kk0]);
                wP1 = *reinterpret_cast<const float4*>(&W[((size_t)h0 * 1024 + kn + bD1) * 64 + kk0]);
            }

#pragma unroll
            for (int q = 0; q < 2; q++) {
                const int kc = q * 8 + tig;
                unsigned a[2][4];
#pragma unroll
                for (int mt = 0; mt < 2; mt++) {
                    const int r0 = wm * 32 + mt * 16 + g;
                    a[mt][0] = Ah[r0][kc];     a[mt][1] = Ah[r0 + 8][kc];
                    a[mt][2] = Ah[r0][kc + 4]; a[mt][3] = Ah[r0 + 8][kc + 4];
                }
#pragma unroll
                for (int nt = 0; nt < 8; nt++) {
                    const int col = wn * 64 + nt * 8 + g;
                    unsigned b0 = Bh[kc][col], b1 = Bh[kc + 4][col];
#pragma unroll
                    for (int mt = 0; mt < 2; mt++) {
                        float* c = acc[mt][nt];
                        mma_tf(c[0], c[1], c[2], c[3], a[mt][0], a[mt][1], a[mt][2], a[mt][3], b0, b1);
                    }
                }
            }
            __syncthreads();
        }

#pragma unroll
        for (int mt = 0; mt < 2; mt++) {
            const int m0 = cRow * 128 + wm * 32 + mt * 16 + g;
#pragma unroll
            for (int nt = 0; nt < 8; nt++) {
                const int n0 = cCol * 128 + wn * 64 + nt * 8 + 2 * tig;
                const int h = n0 >> 6, kk = n0 & 63;
                const float b0 = bias[n0], b1 = bias[n0 + 1];
#pragma unroll
                for (int rr = 0; rr < 2; rr++) {
                    const int m = m0 + rr * 8;
                    const int b = m >> 10, s = m & 1023;
                    const int bh = b * Hc + h;
                    const int kt = s >> 6, t = s & 63;
                    const int widx = (t >> 3) * 8 + (t & 3) * 2 + ((t >> 2) & 1);
                    const size_t base = (((size_t)bh * 16 + kt) * 64 + kk) * 64 + widx;
                    outV[base]      = f2tf(acc[mt][nt][rr * 2 + 0] + b0);
                    outV[base + 64] = f2tf(acc[mt][nt][rr * 2 + 1] + b1);
                }
            }
        }
        return;
    }

    // ===== Q/K path: pre-split operands, cp.async double buffer, Kt=32 ======
    const unsigned* actH = zz ? g_akh : g_aqh;
    const unsigned* actL = zz ? g_akl : g_aql;
    const unsigned* wgtH = zz ? g_wkh : g_wqh;
    const unsigned* wgtL = zz ? g_wkl : g_wql;
    const float* bias = zz ? bk : bq;

    // staging addressing (per thread)
    const int aR = tid >> 2,  aW4 = (tid & 3) * 4;       // A: 2 cp16 (idx, idx+256)
    const int aR2 = (tid + 256) >> 2;
    const int bKp = tid >> 5, bN4 = (tid & 31) * 4;      // B: 2 cp16
    const int bKp2 = (tid + 256) >> 5;
    const int hB  = cCol * 2 + (bN4 >> 6), colB = bN4 & 63;

    // buffer offsets (words): Ah 0 | Al 2560 | Bh 5120 | Bl 7232 ; stride 9344
#define ISSUE_TILE(buf, ktile)                                                   \
    {                                                                            \
        unsigned* Ah_ = sm + (buf) * 9344;                                       \
        unsigned* Al_ = Ah_ + 2560;                                              \
        unsigned* Bh_ = Ah_ + 5120;                                              \
        unsigned* Bl_ = Ah_ + 7232;                                              \
        const int k0h = (ktile) * 16;                                            \
        cp16(&Ah_[aR * 20 + aW4],  &actH[(size_t)(cRow * 128 + aR) * 512 + k0h + aW4]);   \
        cp16(&Ah_[aR2 * 20 + aW4], &actH[(size_t)(cRow * 128 + aR2) * 512 + k0h + aW4]);  \
        cp16(&Al_[aR * 20 + aW4],  &actL[(size_t)(cRow * 128 + aR) * 512 + k0h + aW4]);   \
        cp16(&Al_[aR2 * 20 + aW4], &actL[(size_t)(cRow * 128 + aR2) * 512 + k0h + aW4]);  \
        cp16(&Bh_[bKp * 132 + bN4],  &wgtH[((size_t)hB * 512 + k0h + bKp) * 64 + colB]);  \
        cp16(&Bh_[bKp2 * 132 + bN4], &wgtH[((size_t)hB * 512 + k0h + bKp2) * 64 + colB]); \
        cp16(&Bl_[bKp * 132 + bN4],  &wgtL[((size_t)hB * 512 + k0h + bKp) * 64 + colB]);  \
        cp16(&Bl_[bKp2 * 132 + bN4], &wgtL[((size_t)hB * 512 + k0h + bKp2) * 64 + colB]); \
        asm volatile("cp.async.commit_group;" ::: "memory");                     \
    }

    ISSUE_TILE(0, 0)

    for (int kt = 0; kt < 32; kt++) {
        const int b = kt & 1;
        asm volatile("cp.async.wait_group 0;" ::: "memory");
        __syncthreads();

        if (kt < 31) ISSUE_TILE(b ^ 1, kt + 1)

        unsigned* Ah_ = sm + b * 9344;
        unsigned* Al_ = Ah_ + 2560;
        unsigned* Bh_ = Ah_ + 5120;
        unsigned* Bl_ = Ah_ + 7232;

#pragma unroll
        for (int q = 0; q < 2; q++) {
            const int kc = q * 8 + tig;
            unsigned ah[2][4], al[2][4];
#pragma unroll
            for (int mt = 0; mt < 2; mt++) {
                const int r0 = wm * 32 + mt * 16 + g;
                ah[mt][0] = Ah_[r0 * 20 + kc];           ah[mt][1] = Ah_[(r0 + 8) * 20 + kc];
                ah[mt][2] = Ah_[r0 * 20 + kc + 4];       ah[mt][3] = Ah_[(r0 + 8) * 20 + kc + 4];
                al[mt][0] = Al_[r0 * 20 + kc];           al[mt][1] = Al_[(r0 + 8) * 20 + kc];
                al[mt][2] = Al_[r0 * 20 + kc + 4];       al[mt][3] = Al_[(r0 + 8) * 20 + kc + 4];
            }
#pragma unroll
            for (int nt = 0; nt < 8; nt++) {
                const int col = wn * 64 + nt * 8 + g;
                unsigned b0h = Bh_[kc * 132 + col], b1h = Bh_[(kc + 4) * 132 + col];
                unsigned b0l = Bl_[kc * 132 + col], b1l = Bl_[(kc + 4) * 132 + col];
#pragma unroll
                for (int mt = 0; mt < 2; mt++) {
                    float* c = acc[mt][nt];
                    mma_bf(c[0], c[1], c[2], c[3], ah[mt][0], ah[mt][1], ah[mt][2], ah[mt][3], b0h, b1h);
                    mma_bf(c[0], c[1], c[2], c[3], ah[mt][0], ah[mt][1], ah[mt][2], ah[mt][3], b0l, b1l);
                    mma_bf(c[0], c[1], c[2], c[3], al[mt][0], al[mt][1], al[mt][2], al[mt][3], b0h, b1h);
                }
            }
        }
    }
#undef ISSUE_TILE

    // Epilogue: bias, split-pack, store to consumption-ordered layouts
#pragma unroll
    for (int mt = 0; mt < 2; mt++) {
        const int m0 = cRow * 128 + wm * 32 + mt * 16 + g;
#pragma unroll
        for (int nt = 0; nt < 8; nt++) {
            const int n0 = cCol * 128 + wn * 64 + nt * 8 + 2 * tig;
            const int h = n0 >> 6, kp = (n0 & 63) >> 1;
            const float b0 = bias[n0], b1 = bias[n0 + 1];
#pragma unroll
            for (int rr = 0; rr < 2; rr++) {
                const int m = m0 + rr * 8;
                const int b = m >> 10, s = m & 1023;
                const int bh = b * Hc + h;
                unsigned hp, lp;
                split_pack(acc[mt][nt][rr * 2 + 0] + b0, acc[mt][nt][rr * 2 + 1] + b1, hp, lp);
                if (zz == 0) {
                    const int grp = s >> 4, gr = s & 7, rb = (s >> 3) & 1;
                    const int qst = kp >> 3, tt = kp & 7;
                    const int slot = tt >> 2, tigr = tt & 3;
                    const size_t entry =
                        (((size_t)bh * 64 + grp) * 4 + qst) * 32 + (gr * 4 + tigr);
                    outQ[entry * 8 + slot * 2 + rb]     = hp;
                    outQ[entry * 8 + 4 + slot * 2 + rb] = lp;
                } else {
                    const int q = kp >> 3, t = kp & 7;
                    const int wpos = (t < 4) ? (q * 16 + t * 4) : (q * 16 + (t & 3) * 4 + 1);
                    const size_t o = ((size_t)bh * Sc + s) * 64 + wpos;
                    outK[o]     = hp;
                    outK[o + 2] = lp;
                }
            }
        }
    }
}

// ---------------------------------------------------------------------------
// Fused attention — R8 verbatim.
// ---------------------------------------------------------------------------
#define FUSED_SMEM 108544

__global__ __launch_bounds__(256, 2) void fused_attn()
{
    extern __shared__ unsigned char smraw[];
    unsigned* Qhf = reinterpret_cast<unsigned*>(smraw);
    unsigned* Qlf = reinterpret_cast<unsigned*>(smraw + 16384);
    unsigned* Ks  = reinterpret_cast<unsigned*>(smraw + 32768);
    unsigned* Vs  = reinterpret_cast<unsigned*>(smraw + 53248);
    unsigned* Ps  = reinterpret_cast<unsigned*>(smraw + 71680);

    const int tid  = threadIdx.x;
    const int lane = tid & 31, warp = tid >> 5;
    const int g = lane >> 2, tig = lane & 3;
    const int qt = blockIdx.x, bh = blockIdx.y;
    const int r0 = warp * 16;

    {
        const uint4* qsrc = reinterpret_cast<const uint4*>(
            g_qf + ((size_t)bh * 64 + qt * 8) * 1024);
#pragma unroll
        for (int i = 0; i < 8; i++) {
            const int idx = tid + i * 256;
            const int entry = idx >> 1;
            unsigned* dst = (idx & 1) ? Qlf : Qhf;
            cp16(&dst[entry * 4], &qsrc[idx]);
        }
    }

    float oacc[8][4];
#pragma unroll
    for (int j = 0; j < 8; j++)
#pragma unroll
        for (int l = 0; l < 4; l++) oacc[j][l] = 0.f;
    float lsum0 = 0.f, lsum1 = 0.f;

    const int sA = qt * 128 + r0 + g;
    const int sB = sA + 8;
    const int rowA = (r0 + g) * 72, rowB = (r0 + g + 8) * 72;

    for (int kt = 0; kt < 16; kt++) {
        {
            const uint4* ksrc = reinterpret_cast<const uint4*>(
                g_kf + ((size_t)bh * Sc + kt * 64) * 64);
            const uint4* vsrc = reinterpret_cast<const uint4*>(
                g_vt + ((size_t)bh * 16 + kt) * 4096);
#pragma unroll
            for (int i = 0; i < 4; i++) {
                const int idx = tid + i * 256;
                const int r = idx >> 4, c4 = (idx & 15) * 4;
                cp16(&Ks[r * 80 + c4], &ksrc[idx]);
                cp16(&Vs[r * 72 + c4], &vsrc[idx]);
            }
        }
        asm volatile("cp.async.commit_group;" ::: "memory");
        asm volatile("cp.async.wait_group 0;" ::: "memory");
        __syncthreads();

        const unsigned wA0 = g_mb[sA][2 * kt], wA1 = g_mb[sA][2 * kt + 1];
        const unsigned wB0 = g_mb[sB][2 * kt], wB1 = g_mb[sB][2 * kt + 1];

        float sacc[8][4];
#pragma unroll
        for (int j = 0; j < 8; j++)
#pragma unroll
            for (int l = 0; l < 4; l++) sacc[j][l] = 0.f;

#pragma unroll
        for (int q = 0; q < 4; q++) {
            const int entry = (warp * 4 + q) * 32 + lane;
            uint4 uh = *reinterpret_cast<const uint4*>(&Qhf[entry * 4]);
            uint4 ul = *reinterpret_cast<const uint4*>(&Qlf[entry * 4]);
#pragma unroll
            for (int nf = 0; nf < 8; nf++) {
                uint4 kb = *reinterpret_cast<const uint4*>(
                    &Ks[(nf * 8 + g) * 80 + q * 16 + tig * 4]);
                float* c = sacc[nf];
                mma_bf(c[0], c[1], c[2], c[3], uh.x, uh.y, uh.z, uh.w, kb.x, kb.y);
                mma_bf(c[0], c[1], c[2], c[3], uh.x, uh.y, uh.z, uh.w, kb.z, kb.w);
                mma_bf(c[0], c[1], c[2], c[3], ul.x, ul.y, ul.z, ul.w, kb.x, kb.y);
            }
        }

        const int wbase = ((2 * tig) & 3) * 2 + (tig >> 1);
#pragma unroll
        for (int nf = 0; nf < 8; nf++) {
            const unsigned w0 = (nf < 4) ? wA0 : wA1;
            const unsigned w1 = (nf < 4) ? wB0 : wB1;
            const int bidx = 8 * (nf & 3) + 2 * tig;
            const float p0 = ((w0 >> bidx) & 1u)       ? __expf(sacc[nf][0] - SHIFT) : 0.f;
            const float p1 = ((w0 >> (bidx + 1)) & 1u) ? __expf(sacc[nf][1] - SHIFT) : 0.f;
            const float p2 = ((w1 >> bidx) & 1u)       ? __expf(sacc[nf][2] - SHIFT) : 0.f;
            const float p3 = ((w1 >> (bidx + 1)) & 1u) ? __expf(sacc[nf][3] - SHIFT) : 0.f;
            lsum0 += p0 + p1;
            lsum1 += p2 + p3;
            const int widx = nf * 8 + wbase;
            Ps[rowA + widx]     = f2tf(p0);
            Ps[rowA + widx + 2] = f2tf(p1);
            Ps[rowB + widx]     = f2tf(p2);
            Ps[rowB + widx + 2] = f2tf(p3);
        }
        __syncwarp();

#pragma unroll
        for (int kc = 0; kc < 8; kc++) {
            uint2 pA = *reinterpret_cast<const uint2*>(&Ps[rowA + kc * 8 + tig * 2]);
            uint2 pB = *reinterpret_cast<const uint2*>(&Ps[rowB + kc * 8 + tig * 2]);
#pragma unroll
            for (int nf = 0; nf < 8; nf++) {
                uint2 vv = *reinterpret_cast<const uint2*>(
                    &Vs[(nf * 8 + g) * 72 + kc * 8 + tig * 2]);
                float* c = oacc[nf];
                mma_tf(c[0], c[1], c[2], c[3], pA.x, pB.x, pA.y, pB.y, vv.x, vv.y);
            }
        }
        __syncthreads();
    }

    lsum0 += __shfl_xor_sync(0xffffffffu, lsum0, 1);
    lsum0 += __shfl_xor_sync(0xffffffffu, lsum0, 2);
    lsum1 += __shfl_xor_sync(0xffffffffu, lsum1, 1);
    lsum1 += __shfl_xor_sync(0xffffffffu, lsum1, 2);
    const float inv0 = 1.0f / lsum0;
    const float inv1 = 1.0f / lsum1;

    const int b = bh >> 4, h = bh & 15;
#pragma unroll
    for (int nf = 0; nf < 8; nf++) {
        const int col = nf * 8 + 2 * tig;
        *reinterpret_cast<float2*>(
            &g_o[(((size_t)b * Sc + sA) * Hc + h) * 64 + col]) =
            make_float2(oacc[nf][0] * inv0, oacc[nf][1] * inv0);
        *reinterpret_cast<float2*>(
            &g_o[(((size_t)b * Sc + sB) * Hc + h) * 64 + col]) =
            make_float2(oacc[nf][2] * inv1, oacc[nf][3] * inv1);
    }
}

// ---------------------------------------------------------------------------
// Final projection: single TF32, Kt=32, reg-prefetch (R8 verbatim).
// ---------------------------------------------------------------------------
__global__ __launch_bounds__(256, 2) void final_mma(
    const float* __restrict__ Wp,
    const float* __restrict__ bp,
    float* __restrict__ out)
{
    __shared__ unsigned As[128][36];
    __shared__ unsigned Bs[32][136];

    const int tid  = threadIdx.x;
    const int lane = tid & 31, warp = tid >> 5;
    const int g = lane >> 2, tig = lane & 3;
    const int wm = warp >> 1, wn = warp & 1;
    const int cRow = blockIdx.y, cCol = blockIdx.x;

    const int aC = (tid & 7) * 4;
    const int bN = (tid & 31) * 4;

    float acc[2][8][4];
#pragma unroll
    for (int i = 0; i < 2; i++)
#pragma unroll
        for (int j = 0; j < 8; j++)
#pragma unroll
            for (int l = 0; l < 4; l++) acc[i][j][l] = 0.f;

    float4 aP[4], wP[4];
#pragma unroll
    for (int i = 0; i < 4; i++) {
        aP[i] = *reinterpret_cast<const float4*>(
            &g_o[(size_t)(cRow * 128 + ((tid + i * 256) >> 3)) * 1024 + aC]);
        wP[i] = *reinterpret_cast<const float4*>(
            &Wp[(size_t)(((tid + i * 256) >> 5)) * 1024 + cCol * 128 + bN]);
    }

    for (int k0 = 0; k0 < 1024; k0 += 32) {
#pragma unroll
        for (int i = 0; i < 4; i++) {
            const int r = (tid + i * 256) >> 3;
            *reinterpret_cast<uint4*>(&As[r][aC]) =
                make_uint4(f2tf(aP[i].x), f2tf(aP[i].y), f2tf(aP[i].z), f2tf(aP[i].w));
            const int d = (tid + i * 256) >> 5;
            *reinterpret_cast<uint4*>(&Bs[d][bN]) =
                make_uint4(f2tf(wP[i].x), f2tf(wP[i].y), f2tf(wP[i].z), f2tf(wP[i].w));
        }
        __syncthreads();

        if (k0 + 32 < 1024) {
            const int kn = k0 + 32;
#pragma unroll
            for (int i = 0; i < 4; i++) {
                aP[i] = *reinterpret_cast<const float4*>(
                    &g_o[(size_t)(cRow * 128 + ((tid + i * 256) >> 3)) * 1024 + kn + aC]);
                wP[i] = *reinterpret_cast<const float4*>(
                    &Wp[(size_t)(kn + ((tid + i * 256) >> 5)) * 1024 + cCol * 128 + bN]);
            }
        }

#pragma unroll
        for (int q = 0; q < 4; q++) {
            const int kc = q * 8 + tig;
            unsigned a[2][4];
#pragma unroll
            for (int mt = 0; mt < 2; mt++) {
                const int r0 = wm * 32 + mt * 16 + g;
                a[mt][0] = As[r0][kc];     a[mt][1] = As[r0 + 8][kc];
                a[mt][2] = As[r0][kc + 4]; a[mt][3] = As[r0 + 8][kc + 4];
            }
#pragma unroll
            for (int nt = 0; nt < 8; nt++) {
                const int col = wn * 64 + nt * 8 + g;
                unsigned b0 = Bs[kc][col], b1 = Bs[kc + 4][col];
#pragma unroll
                for (int mt = 0; mt < 2; mt++) {
                    float* c = acc[mt][nt];
                    mma_tf(c[0], c[1], c[2], c[3], a[mt][0], a[mt][1], a[mt][2], a[mt][3], b0, b1);
                }
            }
        }
        __syncthreads();
    }

#pragma unroll
    for (int mt = 0; mt < 2; mt++) {
        const int m0 = cRow * 128 + wm * 32 + mt * 16 + g;
#pragma unroll
        for (int nt = 0; nt < 8; nt++) {
            const int n0 = cCol * 128 + wn * 64 + nt * 8 + 2 * tig;
            const float b0 = bp[n0], b1 = bp[n0 + 1];
            *reinterpret_cast<float2*>(&out[(size_t)m0 * 1024 + n0]) =
                make_float2(acc[mt][nt][0] + b0, acc[mt][nt][1] + b1);
            *reinterpret_cast<float2*>(&out[(size_t)(m0 + 8) * 1024 + n0]) =
                make_float2(acc[mt][nt][2] + b0, acc[mt][nt][3] + b1);
        }
    }
}

// ---------------------------------------------------------------------------
extern "C" void kernel_launch(void* const* d_in, const int* in_sizes, int n_in,
                              void* d_out, int out_size)
{
    const float* querys = (const float*)d_in[0];
    const float* keys   = (const float*)d_in[1];
    const float* values = (const float*)d_in[2];
    const int*   mask   = (const int*)d_in[3];
    const float* Wq     = (const float*)d_in[4];
    const float* bq     = (const float*)d_in[5];
    const float* Wk     = (const float*)d_in[6];
    const float* bk     = (const float*)d_in[7];
    const float* Wv     = (const float*)d_in[8];
    const float* bv     = (const float*)d_in[9];
    const float* Wp     = (const float*)d_in[10];
    const float* bp     = (const float*)d_in[11];
    float* out = (float*)d_out;

    unsigned *qf = nullptr, *kf = nullptr, *vt = nullptr;
    cudaGetSymbolAddress((void**)&qf, g_qf);
    cudaGetSymbolAddress((void**)&kf, g_kf);
    cudaGetSymbolAddress((void**)&vt, g_vt);

    cudaFuncSetAttribute(fused_attn,
                         cudaFuncAttributeMaxDynamicSharedMemorySize, FUSED_SMEM);
    cudaFuncSetAttribute(qkv_proj,
                         cudaFuncAttributeMaxDynamicSharedMemorySize, QKV_SMEM);

    maskbits_kernel<<<1024, 1024>>>(mask);

    dim3 gSplitA(4096, 1, 2);
    split_act<<<gSplitA, 256>>>(querys, keys);
    dim3 gSplitW(512, 16, 2);
    split_wgt<<<gSplitW, 64>>>(Wq, Wk);

    dim3 gQKV(8, 32, 3);
    qkv_proj<<<gQKV, 256, QKV_SMEM>>>(values, Wv, bq, bk, bv, qf, kf, vt);

    dim3 gAttn(8, 64);
    fused_attn<<<gAttn, 256, FUSED_SMEM>>>();

    dim3 gProj(8, 32);
    final_mma<<<gProj, 256>>>(Wp, bp, out);
}

// round 16
// speedup vs baseline: 1.0230x; 1.0230x over previous
#include <cuda_runtime.h>
#include <cuda_bf16.h>
#include <math.h>

#define Sc 1024
#define Hc 16
#define SHIFT 20.0f

// Scratch (static device globals — allocation-free rule)
__device__ unsigned g_qf[(size_t)64 * 64 * 4 * 32 * 8];     // Q frag-linear 16MB
__device__ unsigned g_kf[(size_t)64 * 1024 * 64];           // K rows 16MB
__device__ unsigned g_vt[(size_t)64 * 16 * 64 * 64];        // V tf32 16MB
__device__ float    g_o [(size_t)4 * 1024 * 1024];          // concat 16MB
__device__ unsigned g_mb[1024][32];                         // mask bitwords
// pre-split Q/K weights (hi/lo bf16x2 of adjacent-d pairs): [16][512][64]
__device__ unsigned g_wqh[(size_t)16 * 512 * 64];
__device__ unsigned g_wql[(size_t)16 * 512 * 64];
__device__ unsigned g_wkh[(size_t)16 * 512 * 64];
__device__ unsigned g_wkl[(size_t)16 * 512 * 64];

__device__ __forceinline__ unsigned f2tf(float x) {
    unsigned r; asm("cvt.rna.tf32.f32 %0, %1;" : "=r"(r) : "f"(x)); return r;
}
__device__ __forceinline__ unsigned pack_bf(float e, float o) {
    unsigned r; asm("cvt.rn.bf16x2.f32 %0, %1, %2;" : "=r"(r) : "f"(o), "f"(e)); return r;
}
__device__ __forceinline__ void split_pack(float e, float o, unsigned& hp, unsigned& lp) {
    hp = pack_bf(e, o);
    float eh = __uint_as_float(hp << 16);
    float oh = __uint_as_float(hp & 0xffff0000u);
    lp = pack_bf(e - eh, o - oh);
}
__device__ __forceinline__ void mma_tf(float& c0, float& c1, float& c2, float& c3,
                                       unsigned a0, unsigned a1, unsigned a2, unsigned a3,
                                       unsigned b0, unsigned b1) {
    asm volatile("mma.sync.aligned.m16n8k8.row.col.f32.tf32.tf32.f32 "
                 "{%0,%1,%2,%3},{%4,%5,%6,%7},{%8,%9},{%0,%1,%2,%3};"
                 : "+f"(c0), "+f"(c1), "+f"(c2), "+f"(c3)
                 : "r"(a0), "r"(a1), "r"(a2), "r"(a3), "r"(b0), "r"(b1));
}
__device__ __forceinline__ void mma_bf(float& c0, float& c1, float& c2, float& c3,
                                       unsigned a0, unsigned a1, unsigned a2, unsigned a3,
                                       unsigned b0, unsigned b1) {
    asm volatile("mma.sync.aligned.m16n8k16.row.col.f32.bf16.bf16.f32 "
                 "{%0,%1,%2,%3},{%4,%5,%6,%7},{%8,%9},{%0,%1,%2,%3};"
                 : "+f"(c0), "+f"(c1), "+f"(c2), "+f"(c3)
                 : "r"(a0), "r"(a1), "r"(a2), "r"(a3), "r"(b0), "r"(b1));
}
__device__ __forceinline__ void cp16(void* smem_dst, const void* gmem_src) {
    unsigned d = (unsigned)__cvta_generic_to_shared(smem_dst);
    asm volatile("cp.async.cg.shared.global [%0], [%1], 16;"
                 :: "r"(d), "l"(gmem_src) : "memory");
}

// ---------------------------------------------------------------------------
__global__ void maskbits_kernel(const int* __restrict__ mask)
{
    const int r = blockIdx.x;
    const int c = threadIdx.x;
    unsigned b = __ballot_sync(0xffffffffu, mask[(size_t)r * 1024 + c] != 0);
    if ((c & 31) == 0) g_mb[r][c >> 5] = b;
}

// ---------------------------------------------------------------------------
// Pre-split Q/K weights: W[16][1024][64] -> hi/lo [16][512][64]
// ---------------------------------------------------------------------------
__global__ void split_wgt(const float* __restrict__ Wq, const float* __restrict__ Wk)
{
    const float* W = blockIdx.z ? Wk : Wq;
    unsigned* oh = blockIdx.z ? g_wkh : g_wqh;
    unsigned* ol = blockIdx.z ? g_wkl : g_wql;
    const int kp = blockIdx.x, h = blockIdx.y, n = threadIdx.x;
    float a = W[((size_t)h * 1024 + 2 * kp) * 64 + n];
    float b = W[((size_t)h * 1024 + 2 * kp + 1) * 64 + n];
    unsigned hp, lp;
    split_pack(a, b, hp, lp);
    oh[((size_t)h * 512 + kp) * 64 + n] = hp;
    ol[((size_t)h * 512 + kp) * 64 + n] = lp;
}

// ---------------------------------------------------------------------------
// QKV projections in ONE launch. z=0/1: Q/K — A split in-kernel (reg-prefetch,
// R13 structure), W loaded PRE-SPLIT (pure uint4 staging). z=2: V — tf32.
// ---------------------------------------------------------------------------
__global__ __launch_bounds__(256, 2) void qkv_proj(
    const float* __restrict__ Aq, const float* __restrict__ Ak,
    const float* __restrict__ Av,
    const float* __restrict__ Wv,
    const float* __restrict__ bq, const float* __restrict__ bk,
    const float* __restrict__ bv,
    unsigned* __restrict__ outQ, unsigned* __restrict__ outK,
    unsigned* __restrict__ outV)
{
    __shared__ unsigned sm[9344];   // max of both paths' tile layouts

    const int tid  = threadIdx.x;
    const int lane = tid & 31, warp = tid >> 5;
    const int g = lane >> 2, tig = lane & 3;
    const int wm = warp >> 1, wn = warp & 1;
    const int cRow = blockIdx.y, cCol = blockIdx.x;
    const int zz = blockIdx.z;

    float acc[2][8][4];
#pragma unroll
    for (int i = 0; i < 2; i++)
#pragma unroll
        for (int j = 0; j < 8; j++)
#pragma unroll
            for (int l = 0; l < 4; l++) acc[i][j][l] = 0.f;

    if (zz == 2) {
        // ================= V path: single TF32, Kt=16 (R13 body) ============
        unsigned (*Ah)[20]  = reinterpret_cast<unsigned(*)[20]>(sm);
        unsigned (*Bh)[136] = reinterpret_cast<unsigned(*)[136]>(sm + 2560);

        const float* A = Av; const float* W = Wv; const float* bias = bv;

        const int aR0 = tid >> 2,         aC0 = (tid & 3) * 4;
        const int aR1 = (tid + 256) >> 2, aC1 = aC0;
        const int bD0 = tid >> 5,         bN0 = (tid & 31) * 4;
        const int bD1 = (tid + 256) >> 5, bN1 = bN0;
        const int n0g = cCol * 128 + bN0, h0 = n0g >> 6, kk0 = n0g & 63;

        float4 aP0 = *reinterpret_cast<const float4*>(&A[(size_t)(cRow * 128 + aR0) * 1024 + aC0]);
        float4 aP1 = *reinterpret_cast<const float4*>(&A[(size_t)(cRow * 128 + aR1) * 1024 + aC1]);
        float4 wP0 = *reinterpret_cast<const float4*>(&W[((size_t)h0 * 1024 + bD0) * 64 + kk0]);
        float4 wP1 = *reinterpret_cast<const float4*>(&W[((size_t)h0 * 1024 + bD1) * 64 + kk0]);

        for (int k0 = 0; k0 < 1024; k0 += 16) {
            *reinterpret_cast<uint4*>(&Ah[aR0][aC0]) =
                make_uint4(f2tf(aP0.x), f2tf(aP0.y), f2tf(aP0.z), f2tf(aP0.w));
            *reinterpret_cast<uint4*>(&Ah[aR1][aC1]) =
                make_uint4(f2tf(aP1.x), f2tf(aP1.y), f2tf(aP1.z), f2tf(aP1.w));
            *reinterpret_cast<uint4*>(&Bh[bD0][bN0]) =
                make_uint4(f2tf(wP0.x), f2tf(wP0.y), f2tf(wP0.z), f2tf(wP0.w));
            *reinterpret_cast<uint4*>(&Bh[bD1][bN1]) =
                make_uint4(f2tf(wP1.x), f2tf(wP1.y), f2tf(wP1.z), f2tf(wP1.w));
            __syncthreads();

            if (k0 + 16 < 1024) {
                const int kn = k0 + 16;
                aP0 = *reinterpret_cast<const float4*>(&A[(size_t)(cRow * 128 + aR0) * 1024 + kn + aC0]);
                aP1 = *reinterpret_cast<const float4*>(&A[(size_t)(cRow * 128 + aR1) * 1024 + kn + aC1]);
                wP0 = *reinterpret_cast<const float4*>(&W[((size_t)h0 * 1024 + kn + bD0) * 64 + kk0]);
                wP1 = *reinterpret_cast<const float4*>(&W[((size_t)h0 * 1024 + kn + bD1) * 64 + kk0]);
            }

#pragma unroll
            for (int q = 0; q < 2; q++) {
                const int kc = q * 8 + tig;
                unsigned a[2][4];
#pragma unroll
                for (int mt = 0; mt < 2; mt++) {
                    const int r0 = wm * 32 + mt * 16 + g;
                    a[mt][0] = Ah[r0][kc];     a[mt][1] = Ah[r0 + 8][kc];
                    a[mt][2] = Ah[r0][kc + 4]; a[mt][3] = Ah[r0 + 8][kc + 4];
                }
#pragma unroll
                for (int nt = 0; nt < 8; nt++) {
                    const int col = wn * 64 + nt * 8 + g;
                    unsigned b0 = Bh[kc][col], b1 = Bh[kc + 4][col];
#pragma unroll
                    for (int mt = 0; mt < 2; mt++) {
                        float* c = acc[mt][nt];
                        mma_tf(c[0], c[1], c[2], c[3], a[mt][0], a[mt][1], a[mt][2], a[mt][3], b0, b1);
                    }
                }
            }
            __syncthreads();
        }

#pragma unroll
        for (int mt = 0; mt < 2; mt++) {
            const int m0 = cRow * 128 + wm * 32 + mt * 16 + g;
#pragma unroll
            for (int nt = 0; nt < 8; nt++) {
                const int n0 = cCol * 128 + wn * 64 + nt * 8 + 2 * tig;
                const int h = n0 >> 6, kk = n0 & 63;
                const float b0 = bias[n0], b1 = bias[n0 + 1];
#pragma unroll
                for (int rr = 0; rr < 2; rr++) {
                    const int m = m0 + rr * 8;
                    const int b = m >> 10, s = m & 1023;
                    const int bh = b * Hc + h;
                    const int kt = s >> 6, t = s & 63;
                    const int widx = (t >> 3) * 8 + (t & 3) * 2 + ((t >> 2) & 1);
                    const size_t base = (((size_t)bh * 16 + kt) * 64 + kk) * 64 + widx;
                    outV[base]      = f2tf(acc[mt][nt][rr * 2 + 0] + b0);
                    outV[base + 64] = f2tf(acc[mt][nt][rr * 2 + 1] + b1);
                }
            }
        }
        return;
    }

    // ===== Q/K path: A split in-kernel, W pre-split, Kt=32, reg-prefetch ====
    unsigned (*Ah)[20]  = reinterpret_cast<unsigned(*)[20]>(sm);           // 128x20
    unsigned (*Al)[20]  = reinterpret_cast<unsigned(*)[20]>(sm + 2560);    // 128x20
    unsigned (*Bh)[132] = reinterpret_cast<unsigned(*)[132]>(sm + 5120);   // 16x132
    unsigned (*Bl)[132] = reinterpret_cast<unsigned(*)[132]>(sm + 7232);   // 16x132

    const float* A        = zz ? Ak : Aq;
    const unsigned* wgtH  = zz ? g_wkh : g_wqh;
    const unsigned* wgtL  = zz ? g_wkl : g_wql;
    const float* bias     = zz ? bk : bq;

    const int n0g = cCol * 128 + ((tid & 31) * 4);
    const int hB  = n0g >> 6, kkB = n0g & 63;

    float4 aP[4];
    uint4 wPh[2], wPl[2];
#pragma unroll
    for (int i = 0; i < 4; i++) {
        const int idx = tid + i * 256;
        aP[i] = *reinterpret_cast<const float4*>(
            &A[(size_t)(cRow * 128 + (idx >> 3)) * 1024 + (idx & 7) * 4]);
    }
#pragma unroll
    for (int i = 0; i < 2; i++) {
        const int kp = (tid + i * 256) >> 5;
        wPh[i] = *reinterpret_cast<const uint4*>(&wgtH[((size_t)hB * 512 + kp) * 64 + kkB]);
        wPl[i] = *reinterpret_cast<const uint4*>(&wgtL[((size_t)hB * 512 + kp) * 64 + kkB]);
    }

    for (int k0 = 0; k0 < 1024; k0 += 32) {
        // stage A: split + store (unchanged from R13)
#pragma unroll
        for (int i = 0; i < 4; i++) {
            const int idx = tid + i * 256;
            const int r = idx >> 3, kp = (idx & 7) * 2;
            unsigned h0, l0, h1, l1;
            split_pack(aP[i].x, aP[i].y, h0, l0);
            split_pack(aP[i].z, aP[i].w, h1, l1);
            *reinterpret_cast<uint2*>(&Ah[r][kp]) = make_uint2(h0, h1);
            *reinterpret_cast<uint2*>(&Al[r][kp]) = make_uint2(l0, l1);
        }
        // stage B: pure uint4 stores (pre-split)
#pragma unroll
        for (int i = 0; i < 2; i++) {
            const int idx = tid + i * 256;
            const int kp = idx >> 5, n4 = (idx & 31) * 4;
            *reinterpret_cast<uint4*>(&Bh[kp][n4]) = wPh[i];
            *reinterpret_cast<uint4*>(&Bl[kp][n4]) = wPl[i];
        }
        __syncthreads();

        if (k0 + 32 < 1024) {
            const int kn = k0 + 32;
#pragma unroll
            for (int i = 0; i < 4; i++) {
                const int idx = tid + i * 256;
                aP[i] = *reinterpret_cast<const float4*>(
                    &A[(size_t)(cRow * 128 + (idx >> 3)) * 1024 + kn + (idx & 7) * 4]);
            }
            const int kpb = kn >> 1;
#pragma unroll
            for (int i = 0; i < 2; i++) {
                const int kp = kpb + ((tid + i * 256) >> 5);
                wPh[i] = *reinterpret_cast<const uint4*>(&wgtH[((size_t)hB * 512 + kp) * 64 + kkB]);
                wPl[i] = *reinterpret_cast<const uint4*>(&wgtL[((size_t)hB * 512 + kp) * 64 + kkB]);
            }
        }

#pragma unroll
        for (int q = 0; q < 2; q++) {
            const int kc = q * 8 + tig;
            unsigned ah[2][4], al[2][4];
#pragma unroll
            for (int mt = 0; mt < 2; mt++) {
                const int r0 = wm * 32 + mt * 16 + g;
                ah[mt][0] = Ah[r0][kc];     ah[mt][1] = Ah[r0 + 8][kc];
                ah[mt][2] = Ah[r0][kc + 4]; ah[mt][3] = Ah[r0 + 8][kc + 4];
                al[mt][0] = Al[r0][kc];     al[mt][1] = Al[r0 + 8][kc];
                al[mt][2] = Al[r0][kc + 4]; al[mt][3] = Al[r0 + 8][kc + 4];
            }
#pragma unroll
            for (int nt = 0; nt < 8; nt++) {
                const int col = wn * 64 + nt * 8 + g;
                unsigned b0h = Bh[kc][col], b1h = Bh[kc + 4][col];
                unsigned b0l = Bl[kc][col], b1l = Bl[kc + 4][col];
#pragma unroll
                for (int mt = 0; mt < 2; mt++) {
                    float* c = acc[mt][nt];
                    mma_bf(c[0], c[1], c[2], c[3], ah[mt][0], ah[mt][1], ah[mt][2], ah[mt][3], b0h, b1h);
                    mma_bf(c[0], c[1], c[2], c[3], ah[mt][0], ah[mt][1], ah[mt][2], ah[mt][3], b0l, b1l);
                    mma_bf(c[0], c[1], c[2], c[3], al[mt][0], al[mt][1], al[mt][2], al[mt][3], b0h, b1h);
                }
            }
        }
        __syncthreads();
    }

    // Epilogue: bias, split-pack, store to consumption-ordered layouts
#pragma unroll
    for (int mt = 0; mt < 2; mt++) {
        const int m0 = cRow * 128 + wm * 32 + mt * 16 + g;
#pragma unroll
        for (int nt = 0; nt < 8; nt++) {
            const int n0 = cCol * 128 + wn * 64 + nt * 8 + 2 * tig;
            const int h = n0 >> 6, kp = (n0 & 63) >> 1;
            const float b0 = bias[n0], b1 = bias[n0 + 1];
#pragma unroll
            for (int rr = 0; rr < 2; rr++) {
                const int m = m0 + rr * 8;
                const int b = m >> 10, s = m & 1023;
                const int bh = b * Hc + h;
                unsigned hp, lp;
                split_pack(acc[mt][nt][rr * 2 + 0] + b0, acc[mt][nt][rr * 2 + 1] + b1, hp, lp);
                if (zz == 0) {
                    const int grp = s >> 4, gr = s & 7, rb = (s >> 3) & 1;
                    const int qst = kp >> 3, tt = kp & 7;
                    const int slot = tt >> 2, tigr = tt & 3;
                    const size_t entry =
                        (((size_t)bh * 64 + grp) * 4 + qst) * 32 + (gr * 4 + tigr);
                    outQ[entry * 8 + slot * 2 + rb]     = hp;
                    outQ[entry * 8 + 4 + slot * 2 + rb] = lp;
                } else {
                    const int q = kp >> 3, t = kp & 7;
                    const int wpos = (t < 4) ? (q * 16 + t * 4) : (q * 16 + (t & 3) * 4 + 1);
                    const size_t o = ((size_t)bh * Sc + s) * 64 + wpos;
                    outK[o]     = hp;
                    outK[o + 2] = lp;
                }
            }
        }
    }
}

// ---------------------------------------------------------------------------
// Fused attention — R8 verbatim.
// ---------------------------------------------------------------------------
#define FUSED_SMEM 108544

__global__ __launch_bounds__(256, 2) void fused_attn()
{
    extern __shared__ unsigned char smraw[];
    unsigned* Qhf = reinterpret_cast<unsigned*>(smraw);
    unsigned* Qlf = reinterpret_cast<unsigned*>(smraw + 16384);
    unsigned* Ks  = reinterpret_cast<unsigned*>(smraw + 32768);
    unsigned* Vs  = reinterpret_cast<unsigned*>(smraw + 53248);
    unsigned* Ps  = reinterpret_cast<unsigned*>(smraw + 71680);

    const int tid  = threadIdx.x;
    const int lane = tid & 31, warp = tid >> 5;
    const int g = lane >> 2, tig = lane & 3;
    const int qt = blockIdx.x, bh = blockIdx.y;
    const int r0 = warp * 16;

    {
        const uint4* qsrc = reinterpret_cast<const uint4*>(
            g_qf + ((size_t)bh * 64 + qt * 8) * 1024);
#pragma unroll
        for (int i = 0; i < 8; i++) {
            const int idx = tid + i * 256;
            const int entry = idx >> 1;
            unsigned* dst = (idx & 1) ? Qlf : Qhf;
            cp16(&dst[entry * 4], &qsrc[idx]);
        }
    }

    float oacc[8][4];
#pragma unroll
    for (int j = 0; j < 8; j++)
#pragma unroll
        for (int l = 0; l < 4; l++) oacc[j][l] = 0.f;
    float lsum0 = 0.f, lsum1 = 0.f;

    const int sA = qt * 128 + r0 + g;
    const int sB = sA + 8;
    const int rowA = (r0 + g) * 72, rowB = (r0 + g + 8) * 72;

    for (int kt = 0; kt < 16; kt++) {
        {
            const uint4* ksrc = reinterpret_cast<const uint4*>(
                g_kf + ((size_t)bh * Sc + kt * 64) * 64);
            const uint4* vsrc = reinterpret_cast<const uint4*>(
                g_vt + ((size_t)bh * 16 + kt) * 4096);
#pragma unroll
            for (int i = 0; i < 4; i++) {
                const int idx = tid + i * 256;
                const int r = idx >> 4, c4 = (idx & 15) * 4;
                cp16(&Ks[r * 80 + c4], &ksrc[idx]);
                cp16(&Vs[r * 72 + c4], &vsrc[idx]);
            }
        }
        asm volatile("cp.async.commit_group;" ::: "memory");
        asm volatile("cp.async.wait_group 0;" ::: "memory");
        __syncthreads();

        const unsigned wA0 = g_mb[sA][2 * kt], wA1 = g_mb[sA][2 * kt + 1];
        const unsigned wB0 = g_mb[sB][2 * kt], wB1 = g_mb[sB][2 * kt + 1];

        float sacc[8][4];
#pragma unroll
        for (int j = 0; j < 8; j++)
#pragma unroll
            for (int l = 0; l < 4; l++) sacc[j][l] = 0.f;

#pragma unroll
        for (int q = 0; q < 4; q++) {
            const int entry = (warp * 4 + q) * 32 + lane;
            uint4 uh = *reinterpret_cast<const uint4*>(&Qhf[entry * 4]);
            uint4 ul = *reinterpret_cast<const uint4*>(&Qlf[entry * 4]);
#pragma unroll
            for (int nf = 0; nf < 8; nf++) {
                uint4 kb = *reinterpret_cast<const uint4*>(
                    &Ks[(nf * 8 + g) * 80 + q * 16 + tig * 4]);
                float* c = sacc[nf];
                mma_bf(c[0], c[1], c[2], c[3], uh.x, uh.y, uh.z, uh.w, kb.x, kb.y);
                mma_bf(c[0], c[1], c[2], c[3], uh.x, uh.y, uh.z, uh.w, kb.z, kb.w);
                mma_bf(c[0], c[1], c[2], c[3], ul.x, ul.y, ul.z, ul.w, kb.x, kb.y);
            }
        }

        const int wbase = ((2 * tig) & 3) * 2 + (tig >> 1);
#pragma unroll
        for (int nf = 0; nf < 8; nf++) {
            const unsigned w0 = (nf < 4) ? wA0 : wA1;
            const unsigned w1 = (nf < 4) ? wB0 : wB1;
            const int bidx = 8 * (nf & 3) + 2 * tig;
            const float p0 = ((w0 >> bidx) & 1u)       ? __expf(sacc[nf][0] - SHIFT) : 0.f;
            const float p1 = ((w0 >> (bidx + 1)) & 1u) ? __expf(sacc[nf][1] - SHIFT) : 0.f;
            const float p2 = ((w1 >> bidx) & 1u)       ? __expf(sacc[nf][2] - SHIFT) : 0.f;
            const float p3 = ((w1 >> (bidx + 1)) & 1u) ? __expf(sacc[nf][3] - SHIFT) : 0.f;
            lsum0 += p0 + p1;
            lsum1 += p2 + p3;
            const int widx = nf * 8 + wbase;
            Ps[rowA + widx]     = f2tf(p0);
            Ps[rowA + widx + 2] = f2tf(p1);
            Ps[rowB + widx]     = f2tf(p2);
            Ps[rowB + widx + 2] = f2tf(p3);
        }
        __syncwarp();

#pragma unroll
        for (int kc = 0; kc < 8; kc++) {
            uint2 pA = *reinterpret_cast<const uint2*>(&Ps[rowA + kc * 8 + tig * 2]);
            uint2 pB = *reinterpret_cast<const uint2*>(&Ps[rowB + kc * 8 + tig * 2]);
#pragma unroll
            for (int nf = 0; nf < 8; nf++) {
                uint2 vv = *reinterpret_cast<const uint2*>(
                    &Vs[(nf * 8 + g) * 72 + kc * 8 + tig * 2]);
                float* c = oacc[nf];
                mma_tf(c[0], c[1], c[2], c[3], pA.x, pB.x, pA.y, pB.y, vv.x, vv.y);
            }
        }
        __syncthreads();
    }

    lsum0 += __shfl_xor_sync(0xffffffffu, lsum0, 1);
    lsum0 += __shfl_xor_sync(0xffffffffu, lsum0, 2);
    lsum1 += __shfl_xor_sync(0xffffffffu, lsum1, 1);
    lsum1 += __shfl_xor_sync(0xffffffffu, lsum1, 2);
    const float inv0 = 1.0f / lsum0;
    const float inv1 = 1.0f / lsum1;

    const int b = bh >> 4, h = bh & 15;
#pragma unroll
    for (int nf = 0; nf < 8; nf++) {
        const int col = nf * 8 + 2 * tig;
        *reinterpret_cast<float2*>(
            &g_o[(((size_t)b * Sc + sA) * Hc + h) * 64 + col]) =
            make_float2(oacc[nf][0] * inv0, oacc[nf][1] * inv0);
        *reinterpret_cast<float2*>(
            &g_o[(((size_t)b * Sc + sB) * Hc + h) * 64 + col]) =
            make_float2(oacc[nf][2] * inv1, oacc[nf][3] * inv1);
    }
}

// ---------------------------------------------------------------------------
// Final projection: single TF32, Kt=32, reg-prefetch (R8 verbatim).
// ---------------------------------------------------------------------------
__global__ __launch_bounds__(256, 2) void final_mma(
    const float* __restrict__ Wp,
    const float* __restrict__ bp,
    float* __restrict__ out)
{
    __shared__ unsigned As[128][36];
    __shared__ unsigned Bs[32][136];

    const int tid  = threadIdx.x;
    const int lane = tid & 31, warp = tid >> 5;
    const int g = lane >> 2, tig = lane & 3;
    const int wm = warp >> 1, wn = warp & 1;
    const int cRow = blockIdx.y, cCol = blockIdx.x;

    const int aC = (tid & 7) * 4;
    const int bN = (tid & 31) * 4;

    float acc[2][8][4];
#pragma unroll
    for (int i = 0; i < 2; i++)
#pragma unroll
        for (int j = 0; j < 8; j++)
#pragma unroll
            for (int l = 0; l < 4; l++) acc[i][j][l] = 0.f;

    float4 aP[4], wP[4];
#pragma unroll
    for (int i = 0; i < 4; i++) {
        aP[i] = *reinterpret_cast<const float4*>(
            &g_o[(size_t)(cRow * 128 + ((tid + i * 256) >> 3)) * 1024 + aC]);
        wP[i] = *reinterpret_cast<const float4*>(
            &Wp[(size_t)(((tid + i * 256) >> 5)) * 1024 + cCol * 128 + bN]);
    }

    for (int k0 = 0; k0 < 1024; k0 += 32) {
#pragma unroll
        for (int i = 0; i < 4; i++) {
            const int r = (tid + i * 256) >> 3;
            *reinterpret_cast<uint4*>(&As[r][aC]) =
                make_uint4(f2tf(aP[i].x), f2tf(aP[i].y), f2tf(aP[i].z), f2tf(aP[i].w));
            const int d = (tid + i * 256) >> 5;
            *reinterpret_cast<uint4*>(&Bs[d][bN]) =
                make_uint4(f2tf(wP[i].x), f2tf(wP[i].y), f2tf(wP[i].z), f2tf(wP[i].w));
        }
        __syncthreads();

        if (k0 + 32 < 1024) {
            const int kn = k0 + 32;
#pragma unroll
            for (int i = 0; i < 4; i++) {
                aP[i] = *reinterpret_cast<const float4*>(
                    &g_o[(size_t)(cRow * 128 + ((tid + i * 256) >> 3)) * 1024 + kn + aC]);
                wP[i] = *reinterpret_cast<const float4*>(
                    &Wp[(size_t)(kn + ((tid + i * 256) >> 5)) * 1024 + cCol * 128 + bN]);
            }
        }

#pragma unroll
        for (int q = 0; q < 4; q++) {
            const int kc = q * 8 + tig;
            unsigned a[2][4];
#pragma unroll
            for (int mt = 0; mt < 2; mt++) {
                const int r0 = wm * 32 + mt * 16 + g;
                a[mt][0] = As[r0][kc];     a[mt][1] = As[r0 + 8][kc];
                a[mt][2] = As[r0][kc + 4]; a[mt][3] = As[r0 + 8][kc + 4];
            }
#pragma unroll
            for (int nt = 0; nt < 8; nt++) {
                const int col = wn * 64 + nt * 8 + g;
                unsigned b0 = Bs[kc][col], b1 = Bs[kc + 4][col];
#pragma unroll
                for (int mt = 0; mt < 2; mt++) {
                    float* c = acc[mt][nt];
                    mma_tf(c[0], c[1], c[2], c[3], a[mt][0], a[mt][1], a[mt][2], a[mt][3], b0, b1);
                }
            }
        }
        __syncthreads();
    }

#pragma unroll
    for (int mt = 0; mt < 2; mt++) {
        const int m0 = cRow * 128 + wm * 32 + mt * 16 + g;
#pragma unroll
        for (int nt = 0; nt < 8; nt++) {
            const int n0 = cCol * 128 + wn * 64 + nt * 8 + 2 * tig;
            const float b0 = bp[n0], b1 = bp[n0 + 1];
            *reinterpret_cast<float2*>(&out[(size_t)m0 * 1024 + n0]) =
                make_float2(acc[mt][nt][0] + b0, acc[mt][nt][1] + b1);
            *reinterpret_cast<float2*>(&out[(size_t)(m0 + 8) * 1024 + n0]) =
                make_float2(acc[mt][nt][2] + b0, acc[mt][nt][3] + b1);
        }
    }
}

// ---------------------------------------------------------------------------
extern "C" void kernel_launch(void* const* d_in, const int* in_sizes, int n_in,
                              void* d_out, int out_size)
{
    const float* querys = (const float*)d_in[0];
    const float* keys   = (const float*)d_in[1];
    const float* values = (const float*)d_in[2];
    const int*   mask   = (const int*)d_in[3];
    const float* Wq     = (const float*)d_in[4];
    const float* bq     = (const float*)d_in[5];
    const float* Wk     = (const float*)d_in[6];
    const float* bk     = (const float*)d_in[7];
    const float* Wv     = (const float*)d_in[8];
    const float* bv     = (const float*)d_in[9];
    const float* Wp     = (const float*)d_in[10];
    const float* bp     = (const float*)d_in[11];
    float* out = (float*)d_out;

    unsigned *qf = nullptr, *kf = nullptr, *vt = nullptr;
    cudaGetSymbolAddress((void**)&qf, g_qf);
    cudaGetSymbolAddress((void**)&kf, g_kf);
    cudaGetSymbolAddress((void**)&vt, g_vt);

    cudaFuncSetAttribute(fused_attn,
                         cudaFuncAttributeMaxDynamicSharedMemorySize, FUSED_SMEM);

    maskbits_kernel<<<1024, 1024>>>(mask);

    dim3 gSplitW(512, 16, 2);
    split_wgt<<<gSplitW, 64>>>(Wq, Wk);

    dim3 gQKV(8, 32, 3);
    qkv_proj<<<gQKV, 256>>>(querys, keys, values, Wv,
                            bq, bk, bv, qf, kf, vt);

    dim3 gAttn(8, 64);
    fused_attn<<<gAttn, 256, FUSED_SMEM>>>();

    dim3 gProj(8, 32);
    final_mma<<<gProj, 256>>>(Wp, bp, out);
}

// round 17
// speedup vs baseline: 1.0519x; 1.0282x over previous
#include <cuda_runtime.h>
#include <cuda_bf16.h>
#include <math.h>

#define Sc 1024
#define Hc 16
#define SHIFT 20.0f

// Scratch (static device globals — allocation-free rule)
// Q: fragment-linear: [bh][grp 64][q 4][lane 32][8 words: hi0..3, lo0..3]
__device__ unsigned g_qf[(size_t)64 * 64 * 4 * 32 * 8];     // 16MB
// K: staging-ready rows: [bh][s][64 words: [q4][tig4][h,h+4,l,l+4]]
__device__ unsigned g_kf[(size_t)64 * 1024 * 64];           // 16MB
// V: tf32, transposed+interleaved per 64-row tile: [bh][kt 16][col 64][64 words]
__device__ unsigned g_vt[(size_t)64 * 16 * 64 * 64];        // 16MB
__device__ float    g_o [(size_t)4 * 1024 * 1024];          // concat [B][S][H*64]
__device__ unsigned g_mb[1024][32];                         // mask bitwords

__device__ __forceinline__ unsigned f2tf(float x) {
    unsigned r; asm("cvt.rna.tf32.f32 %0, %1;" : "=r"(r) : "f"(x)); return r;
}
__device__ __forceinline__ unsigned pack_bf(float e, float o) {
    unsigned r; asm("cvt.rn.bf16x2.f32 %0, %1, %2;" : "=r"(r) : "f"(o), "f"(e)); return r;
}
__device__ __forceinline__ void split_pack(float e, float o, unsigned& hp, unsigned& lp) {
    hp = pack_bf(e, o);
    float eh = __uint_as_float(hp << 16);
    float oh = __uint_as_float(hp & 0xffff0000u);
    lp = pack_bf(e - eh, o - oh);
}
__device__ __forceinline__ void mma_tf(float& c0, float& c1, float& c2, float& c3,
                                       unsigned a0, unsigned a1, unsigned a2, unsigned a3,
                                       unsigned b0, unsigned b1) {
    asm volatile("mma.sync.aligned.m16n8k8.row.col.f32.tf32.tf32.f32 "
                 "{%0,%1,%2,%3},{%4,%5,%6,%7},{%8,%9},{%0,%1,%2,%3};"
                 : "+f"(c0), "+f"(c1), "+f"(c2), "+f"(c3)
                 : "r"(a0), "r"(a1), "r"(a2), "r"(a3), "r"(b0), "r"(b1));
}
__device__ __forceinline__ void mma_bf(float& c0, float& c1, float& c2, float& c3,
                                       unsigned a0, unsigned a1, unsigned a2, unsigned a3,
                                       unsigned b0, unsigned b1) {
    asm volatile("mma.sync.aligned.m16n8k16.row.col.f32.bf16.bf16.f32 "
                 "{%0,%1,%2,%3},{%4,%5,%6,%7},{%8,%9},{%0,%1,%2,%3};"
                 : "+f"(c0), "+f"(c1), "+f"(c2), "+f"(c3)
                 : "r"(a0), "r"(a1), "r"(a2), "r"(a3), "r"(b0), "r"(b1));
}
__device__ __forceinline__ void cp16(void* smem_dst, const void* gmem_src) {
    unsigned d = (unsigned)__cvta_generic_to_shared(smem_dst);
    asm volatile("cp.async.cg.shared.global [%0], [%1], 16;"
                 :: "r"(d), "l"(gmem_src) : "memory");
}

// ---------------------------------------------------------------------------
__global__ void maskbits_kernel(const int* __restrict__ mask)
{
    const int r = blockIdx.x;
    const int c = threadIdx.x;
    unsigned b = __ballot_sync(0xffffffffu, mask[(size_t)r * 1024 + c] != 0);
    if ((c & 31) == 0) g_mb[r][c >> 5] = b;
}

// ---------------------------------------------------------------------------
// QKV projections in ONE launch. z=0: Q (bf16 3-term split), z=1: K (same),
// z=2: V (tf32 single). R13-verbatim bodies.
// ---------------------------------------------------------------------------
__global__ __launch_bounds__(256, 2) void qkv_proj(
    const float* __restrict__ Aq, const float* __restrict__ Ak,
    const float* __restrict__ Av,
    const float* __restrict__ Wq, const float* __restrict__ Wk,
    const float* __restrict__ Wv,
    const float* __restrict__ bq, const float* __restrict__ bk,
    const float* __restrict__ bv,
    unsigned* __restrict__ outQ, unsigned* __restrict__ outK,
    unsigned* __restrict__ outV)
{
    __shared__ unsigned sm[9344];   // max of both paths' tile layouts

    const int tid  = threadIdx.x;
    const int lane = tid & 31, warp = tid >> 5;
    const int g = lane >> 2, tig = lane & 3;
    const int wm = warp >> 1, wn = warp & 1;
    const int cRow = blockIdx.y, cCol = blockIdx.x;
    const int zz = blockIdx.z;

    float acc[2][8][4];
#pragma unroll
    for (int i = 0; i < 2; i++)
#pragma unroll
        for (int j = 0; j < 8; j++)
#pragma unroll
            for (int l = 0; l < 4; l++) acc[i][j][l] = 0.f;

    if (zz == 2) {
        // ================= V path: single TF32, Kt=16 ======================
        unsigned (*Ah)[20]  = reinterpret_cast<unsigned(*)[20]>(sm);
        unsigned (*Bh)[136] = reinterpret_cast<unsigned(*)[136]>(sm + 2560);

        const float* A = Av; const float* W = Wv; const float* bias = bv;

        const int aR0 = tid >> 2,         aC0 = (tid & 3) * 4;
        const int aR1 = (tid + 256) >> 2, aC1 = aC0;
        const int bD0 = tid >> 5,         bN0 = (tid & 31) * 4;
        const int bD1 = (tid + 256) >> 5, bN1 = bN0;
        const int n0g = cCol * 128 + bN0, h0 = n0g >> 6, kk0 = n0g & 63;

        float4 aP0 = *reinterpret_cast<const float4*>(&A[(size_t)(cRow * 128 + aR0) * 1024 + aC0]);
        float4 aP1 = *reinterpret_cast<const float4*>(&A[(size_t)(cRow * 128 + aR1) * 1024 + aC1]);
        float4 wP0 = *reinterpret_cast<const float4*>(&W[((size_t)h0 * 1024 + bD0) * 64 + kk0]);
        float4 wP1 = *reinterpret_cast<const float4*>(&W[((size_t)h0 * 1024 + bD1) * 64 + kk0]);

        for (int k0 = 0; k0 < 1024; k0 += 16) {
            *reinterpret_cast<uint4*>(&Ah[aR0][aC0]) =
                make_uint4(f2tf(aP0.x), f2tf(aP0.y), f2tf(aP0.z), f2tf(aP0.w));
            *reinterpret_cast<uint4*>(&Ah[aR1][aC1]) =
                make_uint4(f2tf(aP1.x), f2tf(aP1.y), f2tf(aP1.z), f2tf(aP1.w));
            *reinterpret_cast<uint4*>(&Bh[bD0][bN0]) =
                make_uint4(f2tf(wP0.x), f2tf(wP0.y), f2tf(wP0.z), f2tf(wP0.w));
            *reinterpret_cast<uint4*>(&Bh[bD1][bN1]) =
                make_uint4(f2tf(wP1.x), f2tf(wP1.y), f2tf(wP1.z), f2tf(wP1.w));
            __syncthreads();

            if (k0 + 16 < 1024) {
                const int kn = k0 + 16;
                aP0 = *reinterpret_cast<const float4*>(&A[(size_t)(cRow * 128 + aR0) * 1024 + kn + aC0]);
                aP1 = *reinterpret_cast<const float4*>(&A[(size_t)(cRow * 128 + aR1) * 1024 + kn + aC1]);
                wP0 = *reinterpret_cast<const float4*>(&W[((size_t)h0 * 1024 + kn + bD0) * 64 + kk0]);
                wP1 = *reinterpret_cast<const float4*>(&W[((size_t)h0 * 1024 + kn + bD1) * 64 + kk0]);
            }

#pragma unroll
            for (int q = 0; q < 2; q++) {
                const int kc = q * 8 + tig;
                unsigned a[2][4];
#pragma unroll
                for (int mt = 0; mt < 2; mt++) {
                    const int r0 = wm * 32 + mt * 16 + g;
                    a[mt][0] = Ah[r0][kc];     a[mt][1] = Ah[r0 + 8][kc];
                    a[mt][2] = Ah[r0][kc + 4]; a[mt][3] = Ah[r0 + 8][kc + 4];
                }
#pragma unroll
                for (int nt = 0; nt < 8; nt++) {
                    const int col = wn * 64 + nt * 8 + g;
                    unsigned b0 = Bh[kc][col], b1 = Bh[kc + 4][col];
#pragma unroll
                    for (int mt = 0; mt < 2; mt++) {
                        float* c = acc[mt][nt];
                        mma_tf(c[0], c[1], c[2], c[3], a[mt][0], a[mt][1], a[mt][2], a[mt][3], b0, b1);
                    }
                }
            }
            __syncthreads();
        }

#pragma unroll
        for (int mt = 0; mt < 2; mt++) {
            const int m0 = cRow * 128 + wm * 32 + mt * 16 + g;
#pragma unroll
            for (int nt = 0; nt < 8; nt++) {
                const int n0 = cCol * 128 + wn * 64 + nt * 8 + 2 * tig;
                const int h = n0 >> 6, kk = n0 & 63;
                const float b0 = bias[n0], b1 = bias[n0 + 1];
#pragma unroll
                for (int rr = 0; rr < 2; rr++) {
                    const int m = m0 + rr * 8;
                    const int b = m >> 10, s = m & 1023;
                    const int bh = b * Hc + h;
                    const int kt = s >> 6, t = s & 63;
                    const int widx = (t >> 3) * 8 + (t & 3) * 2 + ((t >> 2) & 1);
                    const size_t base = (((size_t)bh * 16 + kt) * 64 + kk) * 64 + widx;
                    outV[base]      = f2tf(acc[mt][nt][rr * 2 + 0] + b0);
                    outV[base + 64] = f2tf(acc[mt][nt][rr * 2 + 1] + b1);
                }
            }
        }
        return;
    }

    // ================= Q/K path: 3-term bf16 split, Kt=32 ===================
    unsigned (*Ah)[20]  = reinterpret_cast<unsigned(*)[20]>(sm);           // 128x20
    unsigned (*Al)[20]  = reinterpret_cast<unsigned(*)[20]>(sm + 2560);    // 128x20
    unsigned (*Bh)[132] = reinterpret_cast<unsigned(*)[132]>(sm + 5120);   // 16x132
    unsigned (*Bl)[132] = reinterpret_cast<unsigned(*)[132]>(sm + 7232);   // 16x132

    const float* A    = zz ? Ak : Aq;
    const float* W    = zz ? Wk : Wq;
    const float* bias = zz ? bk : bq;

    const int n0g = cCol * 128 + ((tid & 31) * 4);
    const int hB  = n0g >> 6, kkB = n0g & 63;

    float4 aP[4], wP[2][2];
#pragma unroll
    for (int i = 0; i < 4; i++) {
        const int idx = tid + i * 256;
        aP[i] = *reinterpret_cast<const float4*>(
            &A[(size_t)(cRow * 128 + (idx >> 3)) * 1024 + (idx & 7) * 4]);
    }
#pragma unroll
    for (int i = 0; i < 2; i++) {
        const int idx = tid + i * 256;
        const int kp = idx >> 5;
        wP[i][0] = *reinterpret_cast<const float4*>(&W[((size_t)hB * 1024 + 2 * kp) * 64 + kkB]);
        wP[i][1] = *reinterpret_cast<const float4*>(&W[((size_t)hB * 1024 + 2 * kp + 1) * 64 + kkB]);
    }

    for (int k0 = 0; k0 < 1024; k0 += 32) {
#pragma unroll
        for (int i = 0; i < 4; i++) {
            const int idx = tid + i * 256;
            const int r = idx >> 3, kp = (idx & 7) * 2;
            unsigned h0, l0, h1, l1;
            split_pack(aP[i].x, aP[i].y, h0, l0);
            split_pack(aP[i].z, aP[i].w, h1, l1);
            *reinterpret_cast<uint2*>(&Ah[r][kp]) = make_uint2(h0, h1);
            *reinterpret_cast<uint2*>(&Al[r][kp]) = make_uint2(l0, l1);
        }
#pragma unroll
        for (int i = 0; i < 2; i++) {
            const int idx = tid + i * 256;
            const int kp = idx >> 5, n4 = (idx & 31) * 4;
            float e[4] = {wP[i][0].x, wP[i][0].y, wP[i][0].z, wP[i][0].w};
            float o[4] = {wP[i][1].x, wP[i][1].y, wP[i][1].z, wP[i][1].w};
            unsigned h4[4], l4[4];
#pragma unroll
            for (int j = 0; j < 4; j++) split_pack(e[j], o[j], h4[j], l4[j]);
            *reinterpret_cast<uint4*>(&Bh[kp][n4]) = make_uint4(h4[0], h4[1], h4[2], h4[3]);
            *reinterpret_cast<uint4*>(&Bl[kp][n4]) = make_uint4(l4[0], l4[1], l4[2], l4[3]);
        }
        __syncthreads();

        if (k0 + 32 < 1024) {
            const int kn = k0 + 32;
#pragma unroll
            for (int i = 0; i < 4; i++) {
                const int idx = tid + i * 256;
                aP[i] = *reinterpret_cast<const float4*>(
                    &A[(size_t)(cRow * 128 + (idx >> 3)) * 1024 + kn + (idx & 7) * 4]);
            }
#pragma unroll
            for (int i = 0; i < 2; i++) {
                const int idx = tid + i * 256;
                const int kp = idx >> 5;
                wP[i][0] = *reinterpret_cast<const float4*>(
                    &W[((size_t)hB * 1024 + kn + 2 * kp) * 64 + kkB]);
                wP[i][1] = *reinterpret_cast<const float4*>(
                    &W[((size_t)hB * 1024 + kn + 2 * kp + 1) * 64 + kkB]);
            }
        }

#pragma unroll
        for (int q = 0; q < 2; q++) {
            const int kc = q * 8 + tig;
            unsigned ah[2][4], al[2][4];
#pragma unroll
            for (int mt = 0; mt < 2; mt++) {
                const int r0 = wm * 32 + mt * 16 + g;
                ah[mt][0] = Ah[r0][kc];     ah[mt][1] = Ah[r0 + 8][kc];
                ah[mt][2] = Ah[r0][kc + 4]; ah[mt][3] = Ah[r0 + 8][kc + 4];
                al[mt][0] = Al[r0][kc];     al[mt][1] = Al[r0 + 8][kc];
                al[mt][2] = Al[r0][kc + 4]; al[mt][3] = Al[r0 + 8][kc + 4];
            }
#pragma unroll
            for (int nt = 0; nt < 8; nt++) {
                const int col = wn * 64 + nt * 8 + g;
                unsigned b0h = Bh[kc][col], b1h = Bh[kc + 4][col];
                unsigned b0l = Bl[kc][col], b1l = Bl[kc + 4][col];
#pragma unroll
                for (int mt = 0; mt < 2; mt++) {
                    float* c = acc[mt][nt];
                    mma_bf(c[0], c[1], c[2], c[3], ah[mt][0], ah[mt][1], ah[mt][2], ah[mt][3], b0h, b1h);
                    mma_bf(c[0], c[1], c[2], c[3], ah[mt][0], ah[mt][1], ah[mt][2], ah[mt][3], b0l, b1l);
                    mma_bf(c[0], c[1], c[2], c[3], al[mt][0], al[mt][1], al[mt][2], al[mt][3], b0h, b1h);
                }
            }
        }
        __syncthreads();
    }

    // Epilogue: bias, split-pack, store to consumption-ordered layouts
#pragma unroll
    for (int mt = 0; mt < 2; mt++) {
        const int m0 = cRow * 128 + wm * 32 + mt * 16 + g;
#pragma unroll
        for (int nt = 0; nt < 8; nt++) {
            const int n0 = cCol * 128 + wn * 64 + nt * 8 + 2 * tig;
            const int h = n0 >> 6, kp = (n0 & 63) >> 1;
            const float b0 = bias[n0], b1 = bias[n0 + 1];
#pragma unroll
            for (int rr = 0; rr < 2; rr++) {
                const int m = m0 + rr * 8;
                const int b = m >> 10, s = m & 1023;
                const int bh = b * Hc + h;
                unsigned hp, lp;
                split_pack(acc[mt][nt][rr * 2 + 0] + b0, acc[mt][nt][rr * 2 + 1] + b1, hp, lp);
                if (zz == 0) {
                    const int grp = s >> 4, gr = s & 7, rb = (s >> 3) & 1;
                    const int qst = kp >> 3, tt = kp & 7;
                    const int slot = tt >> 2, tigr = tt & 3;
                    const size_t entry =
                        (((size_t)bh * 64 + grp) * 4 + qst) * 32 + (gr * 4 + tigr);
                    outQ[entry * 8 + slot * 2 + rb]     = hp;
                    outQ[entry * 8 + 4 + slot * 2 + rb] = lp;
                } else {
                    const int q = kp >> 3, t = kp & 7;
                    const int wpos = (t < 4) ? (q * 16 + t * 4) : (q * 16 + (t & 3) * 4 + 1);
                    const size_t o = ((size_t)bh * Sc + s) * 64 + wpos;
                    outK[o]     = hp;
                    outK[o + 2] = lp;
                }
            }
        }
    }
}

// ---------------------------------------------------------------------------
// Fused attention — R8 verbatim: cp.async staging, single group, wait 0.
// smem: Qhf 16384 | Qlf 16384 | Ks 64x80 20480 | Vs 64x72 18432 | Ps 128x72 36864
// total 108544 B, 2 blocks/SM.
// ---------------------------------------------------------------------------
#define FUSED_SMEM 108544

__global__ __launch_bounds__(256, 2) void fused_attn()
{
    extern __shared__ unsigned char smraw[];
    unsigned* Qhf = reinterpret_cast<unsigned*>(smraw);            // [entry][4]
    unsigned* Qlf = reinterpret_cast<unsigned*>(smraw + 16384);
    unsigned* Ks  = reinterpret_cast<unsigned*>(smraw + 32768);    // [64][80]
    unsigned* Vs  = reinterpret_cast<unsigned*>(smraw + 53248);    // [64][72]
    unsigned* Ps  = reinterpret_cast<unsigned*>(smraw + 71680);    // [128][72]

    const int tid  = threadIdx.x;
    const int lane = tid & 31, warp = tid >> 5;
    const int g = lane >> 2, tig = lane & 3;
    const int qt = blockIdx.x, bh = blockIdx.y;
    const int r0 = warp * 16;

    // ---- stage Q (fragment-linear copy via cp.async) ----
    {
        const uint4* qsrc = reinterpret_cast<const uint4*>(
            g_qf + ((size_t)bh * 64 + qt * 8) * 1024);
#pragma unroll
        for (int i = 0; i < 8; i++) {
            const int idx = tid + i * 256;          // 0..2047
            const int entry = idx >> 1;
            unsigned* dst = (idx & 1) ? Qlf : Qhf;
            cp16(&dst[entry * 4], &qsrc[idx]);
        }
    }

    float oacc[8][4];
#pragma unroll
    for (int j = 0; j < 8; j++)
#pragma unroll
        for (int l = 0; l < 4; l++) oacc[j][l] = 0.f;
    float lsum0 = 0.f, lsum1 = 0.f;

    const int sA = qt * 128 + r0 + g;
    const int sB = sA + 8;
    const int rowA = (r0 + g) * 72, rowB = (r0 + g + 8) * 72;

    for (int kt = 0; kt < 16; kt++) {
        // ---- stage K + V via cp.async ----
        {
            const uint4* ksrc = reinterpret_cast<const uint4*>(
                g_kf + ((size_t)bh * Sc + kt * 64) * 64);
            const uint4* vsrc = reinterpret_cast<const uint4*>(
                g_vt + ((size_t)bh * 16 + kt) * 4096);
#pragma unroll
            for (int i = 0; i < 4; i++) {
                const int idx = tid + i * 256;      // 0..1023
                const int r = idx >> 4, c4 = (idx & 15) * 4;
                cp16(&Ks[r * 80 + c4], &ksrc[idx]);
                cp16(&Vs[r * 72 + c4], &vsrc[idx]);
            }
        }
        asm volatile("cp.async.commit_group;" ::: "memory");
        asm volatile("cp.async.wait_group 0;" ::: "memory");
        __syncthreads();

        const unsigned wA0 = g_mb[sA][2 * kt], wA1 = g_mb[sA][2 * kt + 1];
        const unsigned wB0 = g_mb[sB][2 * kt], wB1 = g_mb[sB][2 * kt + 1];

        // ---- S = Q K^T: 4 k16 steps, 3x bf16 split, vectorized frags ----
        float sacc[8][4];
#pragma unroll
        for (int j = 0; j < 8; j++)
#pragma unroll
            for (int l = 0; l < 4; l++) sacc[j][l] = 0.f;

#pragma unroll
        for (int q = 0; q < 4; q++) {
            const int entry = (warp * 4 + q) * 32 + lane;
            uint4 uh = *reinterpret_cast<const uint4*>(&Qhf[entry * 4]);
            uint4 ul = *reinterpret_cast<const uint4*>(&Qlf[entry * 4]);
#pragma unroll
            for (int nf = 0; nf < 8; nf++) {
                uint4 kb = *reinterpret_cast<const uint4*>(
                    &Ks[(nf * 8 + g) * 80 + q * 16 + tig * 4]);
                float* c = sacc[nf];
                mma_bf(c[0], c[1], c[2], c[3], uh.x, uh.y, uh.z, uh.w, kb.x, kb.y);
                mma_bf(c[0], c[1], c[2], c[3], uh.x, uh.y, uh.z, uh.w, kb.z, kb.w);
                mma_bf(c[0], c[1], c[2], c[3], ul.x, ul.y, ul.z, ul.w, kb.x, kb.y);
            }
        }

        // ---- mask + exp + l-sum + stage P (interleaved tf32) ----
        const int wbase = ((2 * tig) & 3) * 2 + (tig >> 1);
#pragma unroll
        for (int nf = 0; nf < 8; nf++) {
            const unsigned w0 = (nf < 4) ? wA0 : wA1;
            const unsigned w1 = (nf < 4) ? wB0 : wB1;
            const int bidx = 8 * (nf & 3) + 2 * tig;
            const float p0 = ((w0 >> bidx) & 1u)       ? __expf(sacc[nf][0] - SHIFT) : 0.f;
            const float p1 = ((w0 >> (bidx + 1)) & 1u) ? __expf(sacc[nf][1] - SHIFT) : 0.f;
            const float p2 = ((w1 >> bidx) & 1u)       ? __expf(sacc[nf][2] - SHIFT) : 0.f;
            const float p3 = ((w1 >> (bidx + 1)) & 1u) ? __expf(sacc[nf][3] - SHIFT) : 0.f;
            lsum0 += p0 + p1;
            lsum1 += p2 + p3;
            const int widx = nf * 8 + wbase;
            Ps[rowA + widx]     = f2tf(p0);
            Ps[rowA + widx + 2] = f2tf(p1);
            Ps[rowB + widx]     = f2tf(p2);
            Ps[rowB + widx + 2] = f2tf(p3);
        }
        __syncwarp();   // P rows are warp-private

        // ---- O += P V (tf32), vectorized frags ----
#pragma unroll
        for (int kc = 0; kc < 8; kc++) {
            uint2 pA = *reinterpret_cast<const uint2*>(&Ps[rowA + kc * 8 + tig * 2]);
            uint2 pB = *reinterpret_cast<const uint2*>(&Ps[rowB + kc * 8 + tig * 2]);
#pragma unroll
            for (int nf = 0; nf < 8; nf++) {
                uint2 vv = *reinterpret_cast<const uint2*>(
                    &Vs[(nf * 8 + g) * 72 + kc * 8 + tig * 2]);
                float* c = oacc[nf];
                mma_tf(c[0], c[1], c[2], c[3], pA.x, pB.x, pA.y, pB.y, vv.x, vv.y);
            }
        }
        __syncthreads();   // before next kt overwrites K/V
    }

    lsum0 += __shfl_xor_sync(0xffffffffu, lsum0, 1);
    lsum0 += __shfl_xor_sync(0xffffffffu, lsum0, 2);
    lsum1 += __shfl_xor_sync(0xffffffffu, lsum1, 1);
    lsum1 += __shfl_xor_sync(0xffffffffu, lsum1, 2);
    const float inv0 = 1.0f / lsum0;
    const float inv1 = 1.0f / lsum1;

    const int b = bh >> 4, h = bh & 15;
#pragma unroll
    for (int nf = 0; nf < 8; nf++) {
        const int col = nf * 8 + 2 * tig;
        *reinterpret_cast<float2*>(
            &g_o[(((size_t)b * Sc + sA) * Hc + h) * 64 + col]) =
            make_float2(oacc[nf][0] * inv0, oacc[nf][1] * inv0);
        *reinterpret_cast<float2*>(
            &g_o[(((size_t)b * Sc + sB) * Hc + h) * 64 + col]) =
            make_float2(oacc[nf][2] * inv1, oacc[nf][3] * inv1);
    }
}

// ---------------------------------------------------------------------------
// Final projection: single TF32, Kt=32, reg-prefetch (R8 verbatim).
// ---------------------------------------------------------------------------
__global__ __launch_bounds__(256, 2) void final_mma(
    const float* __restrict__ Wp,
    const float* __restrict__ bp,
    float* __restrict__ out)
{
    __shared__ unsigned As[128][36];
    __shared__ unsigned Bs[32][136];

    const int tid  = threadIdx.x;
    const int lane = tid & 31, warp = tid >> 5;
    const int g = lane >> 2, tig = lane & 3;
    const int wm = warp >> 1, wn = warp & 1;
    const int cRow = blockIdx.y, cCol = blockIdx.x;

    const int aC = (tid & 7) * 4;
    const int bN = (tid & 31) * 4;

    float acc[2][8][4];
#pragma unroll
    for (int i = 0; i < 2; i++)
#pragma unroll
        for (int j = 0; j < 8; j++)
#pragma unroll
            for (int l = 0; l < 4; l++) acc[i][j][l] = 0.f;

    float4 aP[4], wP[4];
#pragma unroll
    for (int i = 0; i < 4; i++) {
        aP[i] = *reinterpret_cast<const float4*>(
            &g_o[(size_t)(cRow * 128 + ((tid + i * 256) >> 3)) * 1024 + aC]);
        wP[i] = *reinterpret_cast<const float4*>(
            &Wp[(size_t)(((tid + i * 256) >> 5)) * 1024 + cCol * 128 + bN]);
    }

    for (int k0 = 0; k0 < 1024; k0 += 32) {
#pragma unroll
        for (int i = 0; i < 4; i++) {
            const int r = (tid + i * 256) >> 3;
            *reinterpret_cast<uint4*>(&As[r][aC]) =
                make_uint4(f2tf(aP[i].x), f2tf(aP[i].y), f2tf(aP[i].z), f2tf(aP[i].w));
            const int d = (tid + i * 256) >> 5;
            *reinterpret_cast<uint4*>(&Bs[d][bN]) =
                make_uint4(f2tf(wP[i].x), f2tf(wP[i].y), f2tf(wP[i].z), f2tf(wP[i].w));
        }
        __syncthreads();

        if (k0 + 32 < 1024) {
            const int kn = k0 + 32;
#pragma unroll
            for (int i = 0; i < 4; i++) {
                aP[i] = *reinterpret_cast<const float4*>(
                    &g_o[(size_t)(cRow * 128 + ((tid + i * 256) >> 3)) * 1024 + kn + aC]);
                wP[i] = *reinterpret_cast<const float4*>(
                    &Wp[(size_t)(kn + ((tid + i * 256) >> 5)) * 1024 + cCol * 128 + bN]);
            }
        }

#pragma unroll
        for (int q = 0; q < 4; q++) {
            const int kc = q * 8 + tig;
            unsigned a[2][4];
#pragma unroll
            for (int mt = 0; mt < 2; mt++) {
                const int r0 = wm * 32 + mt * 16 + g;
                a[mt][0] = As[r0][kc];     a[mt][1] = As[r0 + 8][kc];
                a[mt][2] = As[r0][kc + 4]; a[mt][3] = As[r0 + 8][kc + 4];
            }
#pragma unroll
            for (int nt = 0; nt < 8; nt++) {
                const int col = wn * 64 + nt * 8 + g;
                unsigned b0 = Bs[kc][col], b1 = Bs[kc + 4][col];
#pragma unroll
                for (int mt = 0; mt < 2; mt++) {
                    float* c = acc[mt][nt];
                    mma_tf(c[0], c[1], c[2], c[3], a[mt][0], a[mt][1], a[mt][2], a[mt][3], b0, b1);
                }
            }
        }
        __syncthreads();
    }

#pragma unroll
    for (int mt = 0; mt < 2; mt++) {
        const int m0 = cRow * 128 + wm * 32 + mt * 16 + g;
#pragma unroll
        for (int nt = 0; nt < 8; nt++) {
            const int n0 = cCol * 128 + wn * 64 + nt * 8 + 2 * tig;
            const float b0 = bp[n0], b1 = bp[n0 + 1];
            *reinterpret_cast<float2*>(&out[(size_t)m0 * 1024 + n0]) =
                make_float2(acc[mt][nt][0] + b0, acc[mt][nt][1] + b1);
            *reinterpret_cast<float2*>(&out[(size_t)(m0 + 8) * 1024 + n0]) =
                make_float2(acc[mt][nt][2] + b0, acc[mt][nt][3] + b1);
        }
    }
}

// ---------------------------------------------------------------------------
extern "C" void kernel_launch(void* const* d_in, const int* in_sizes, int n_in,
                              void* d_out, int out_size)
{
    const float* querys = (const float*)d_in[0];
    const float* keys   = (const float*)d_in[1];
    const float* values = (const float*)d_in[2];
    const int*   mask   = (const int*)d_in[3];
    const float* Wq     = (const float*)d_in[4];
    const float* bq     = (const float*)d_in[5];
    const float* Wk     = (const float*)d_in[6];
    const float* bk     = (const float*)d_in[7];
    const float* Wv     = (const float*)d_in[8];
    const float* bv     = (const float*)d_in[9];
    const float* Wp     = (const float*)d_in[10];
    const float* bp     = (const float*)d_in[11];
    float* out = (float*)d_out;

    unsigned *qf = nullptr, *kf = nullptr, *vt = nullptr;
    cudaGetSymbolAddress((void**)&qf, g_qf);
    cudaGetSymbolAddress((void**)&kf, g_kf);
    cudaGetSymbolAddress((void**)&vt, g_vt);

    cudaFuncSetAttribute(fused_attn,
                         cudaFuncAttributeMaxDynamicSharedMemorySize, FUSED_SMEM);

    maskbits_kernel<<<1024, 1024>>>(mask);

    dim3 gQKV(8, 32, 3);
    qkv_proj<<<gQKV, 256>>>(querys, keys, values, Wq, Wk, Wv,
                            bq, bk, bv, qf, kf, vt);

    dim3 gAttn(8, 64);
    fused_attn<<<gAttn, 256, FUSED_SMEM>>>();

    dim3 gProj(8, 32);
    final_mma<<<gProj, 256>>>(Wp, bp, out);
}